// round 15
// baseline (speedup 1.0000x reference)
#include <cuda_runtime.h>
#include <cuda_fp16.h>
#include <stdint.h>
#include <math.h>

#define MROWS 16384   // B*N
#define DDIM  1024
#define NSEQ  2048
#define NBATCH 8
#define NSEG  32
#define SEGLEN 64     // NSEQ / NSEG

// ---------------- scratch (device globals) ---------------------------------
__device__ __half g_xh[MROWS * DDIM];            // fp16(x)
__device__ __half g_Wh[4 * DDIM * DDIM];         // transposed weights [n][k], fp16 hi
__device__ __half g_Wl[4 * DDIM * DDIM];         // fp16 residual
__device__ __half g_Vh[MROWS * DDIM];            // fp16(V)
__device__ float g_VW[MROWS * DDIM];
__device__ float g_qpart[MROWS * 8];
__device__ float g_kpart[MROWS * 8];
__device__ float g_tQ[MROWS];
__device__ float g_tK[MROWS];
__device__ float g_tKs[NBATCH * NSEQ];      // sorted tK
__device__ float g_E1[NBATCH * NSEQ];       // e^{+2 tKs}
__device__ float g_E2[NBATCH * NSEQ];       // e^{-2 tKs}
__device__ int   g_perm[NBATCH * NSEQ];     // K sort permutation
__device__ float g_tQs[NBATCH * NSEQ];      // sorted tQ
__device__ int   g_qrow[NBATCH * NSEQ];     // Q sort permutation (orig row in batch)
__device__ int   g_rank[NBATCH * NSEQ];     // rank of sorted query
__device__ float g_vsum[NBATCH * DDIM];     // total colsum of VW
__device__ float g_tot2[NBATCH * DDIM];     // total e^{-2tK}-weighted colsum
__device__ float g_s0[NBATCH * NSEG * DDIM];
__device__ float g_s1[NBATCH * NSEG * DDIM];
__device__ float g_s2[NBATCH * NSEG * DDIM];

// ---------------- PTX helpers (base sm_103 target only!) -------------------
__device__ __forceinline__ uint32_t smem_u32(const void* p) {
    uint32_t a;
    asm("{ .reg .u64 t; cvta.to.shared.u64 t, %1; cvt.u32.u64 %0, t; }"
        : "=r"(a) : "l"(p));
    return a;
}
__device__ __forceinline__ void ldsm4(uint32_t* r, uint32_t a) {
    asm volatile("ldmatrix.sync.aligned.m8n8.x4.shared.b16 {%0,%1,%2,%3}, [%4];"
        : "=r"(r[0]), "=r"(r[1]), "=r"(r[2]), "=r"(r[3]) : "r"(a));
}
__device__ __forceinline__ void mma16816(float* c, const uint32_t* a, const uint32_t* b) {
    asm volatile("mma.sync.aligned.m16n8k16.row.col.f32.f16.f16.f32 "
        "{%0,%1,%2,%3},{%4,%5,%6,%7},{%8,%9},{%0,%1,%2,%3};"
        : "+f"(c[0]), "+f"(c[1]), "+f"(c[2]), "+f"(c[3])
        : "r"(a[0]), "r"(a[1]), "r"(a[2]), "r"(a[3]), "r"(b[0]), "r"(b[1]));
}
__device__ __forceinline__ void cpa16(uint32_t dst, const void* src) {
    asm volatile("cp.async.cg.shared.global [%0], [%1], 16;" :: "r"(dst), "l"(src));
}
__device__ __forceinline__ uint32_t h2(float a, float b) {
    __half2 t = __floats2half2_rn(a, b);
    return *reinterpret_cast<uint32_t*>(&t);
}
__device__ __forceinline__ uint32_t sw64(uint32_t off) {
    return off ^ ((off >> 3) & 0x30);
}

// ---------------- prep: x -> fp16 -------------------------------------------
__global__ void __launch_bounds__(256) prep_x(const float* __restrict__ x) {
    size_t i = ((size_t)blockIdx.x * 256 + threadIdx.x) * 4;
    float4 v = *(const float4*)(x + i);
    uint2 o = make_uint2(h2(v.x, v.y), h2(v.z, v.w));
    *(uint2*)(g_xh + i) = o;
}

// ---------------- prep: transpose W -> fp16 hi/lo [n][k] ---------------------
__global__ void __launch_bounds__(256) prep_w(const float* W0, const float* W1,
                                              const float* W2, const float* W3) {
    __shared__ float t[32][33];
    const float* W = blockIdx.z == 0 ? W0 : blockIdx.z == 1 ? W1
                   : blockIdx.z == 2 ? W2 : W3;
    __half* oh = g_Wh + (size_t)blockIdx.z * DDIM * DDIM;
    __half* ol = g_Wl + (size_t)blockIdx.z * DDIM * DDIM;
    int n0 = blockIdx.x * 32, k0 = blockIdx.y * 32;
    int tx = threadIdx.x, ty = threadIdx.y;       // 32 x 8
#pragma unroll
    for (int j = 0; j < 4; j++)
        t[ty + j * 8][tx] = W[(size_t)(k0 + ty + j * 8) * DDIM + n0 + tx];
    __syncthreads();
#pragma unroll
    for (int j = 0; j < 4; j++) {
        int nn = ty + j * 8;
        float v = t[tx][nn];                      // = W[k0+tx][n0+nn]
        __half h = __float2half_rn(v);
        oh[(size_t)(n0 + nn) * DDIM + k0 + tx] = h;
        ol[(size_t)(n0 + nn) * DDIM + k0 + tx] =
            __float2half_rn(v - __half2float(h));
    }
}

// ---------------- HMMA GEMM: 128x128 tile, BK=32, fp16 A + 2-term fp16 B -----
// SW64-swizzled 64B rows, 4-stage cp.async (&3), single sync/iter, 2 CTAs/SM.
// MODE 0: BN+sigmoid -> row sums; fused Q/K via blockIdx.z
// MODE 1: BN+sigmoid -> g_Vh (fp16)
// MODE 2: plain -> g_VW (fp32)
#define TILEB  8192                    // 128 rows * 64B (32 fp16 cols)
#define STAGE  (3 * TILEB)             // 24576 (A, Bh, Bl)
#define NSTG   4
#define BN_OFF (NSTG * STAGE)          // 98304
#define RED_OFF (BN_OFF + 3 * 128 * 4) // 99840
#define GEMM_SMEM (RED_OFF + 256 * 4)  // 100864

template <int MODE>
__global__ void __launch_bounds__(256, 2)
tc_gemm(const __half* __restrict__ A, const __half* __restrict__ Bh0,
        const __half* __restrict__ Bl0,
        const float* __restrict__ mean, const float* __restrict__ gam,
        const float* __restrict__ var, const float* __restrict__ beta,
        float* __restrict__ part,
        const float* __restrict__ mean2, const float* __restrict__ gam2,
        const float* __restrict__ var2, const float* __restrict__ beta2,
        float* __restrict__ part2)
{
    extern __shared__ char smem[];
    const uint32_t sb = smem_u32(smem);
    const int tid = threadIdx.x, lane = tid & 31, wid = tid >> 5;
    const int wm = wid & 3, wn = wid >> 2;        // 4 (M) x 2 (N) warps
    const int bc = blockIdx.x, br = blockIdx.y;
    const int row0 = br * 128, col0 = bc * 128;

    const __half* Bh = Bh0;
    const __half* Bl = Bl0;
    if (MODE == 0 && blockIdx.z == 1) {
        Bh += (size_t)DDIM * DDIM; Bl += (size_t)DDIM * DDIM;
        mean = mean2; gam = gam2; var = var2; beta = beta2; part = part2;
    }

    float* pm = (float*)(smem + BN_OFF);
    float* ps = pm + 128;
    float* pb = ps + 128;
    if (MODE != 2 && tid < 128) {
        pm[tid] = mean[col0 + tid];
        ps[tid] = gam[col0 + tid] * rsqrtf(var[col0 + tid] + 1e-5f);
        pb[tid] = beta[col0 + tid];
    }

    // precomputed swizzled ldmatrix offsets (per-thread loop invariants)
    uint32_t aswz[2][2], bswz[4][2];
#pragma unroll
    for (int mi = 0; mi < 2; mi++)
#pragma unroll
        for (int s = 0; s < 2; s++)
            aswz[mi][s] = sw64((uint32_t)((wm * 32 + mi * 16 + (lane & 15)) * 64
                                          + (2 * s + (lane >> 4)) * 16));
#pragma unroll
    for (int j = 0; j < 4; j++)
#pragma unroll
        for (int s = 0; s < 2; s++)
            bswz[j][s] = sw64((uint32_t)((wn * 64 + j * 16 + (lane & 7) + ((lane >> 4) << 3)) * 64
                                         + (2 * s + ((lane >> 3) & 1)) * 16));

    float acc[2][8][4];
#pragma unroll
    for (int a = 0; a < 2; a++)
#pragma unroll
        for (int b = 0; b < 8; b++)
#pragma unroll
            for (int q = 0; q < 4; q++) acc[a][b][q] = 0.0f;

    // stage loader: 3 tiles of 128x32 fp16
    auto load_stage = [&](int stg, int k) {
        const uint32_t st = sb + stg * STAGE;
#pragma unroll
        for (int tile = 0; tile < 3; tile++) {
            const __half* src = (tile == 0) ? A : (tile == 1) ? Bh : Bl;
            const int r0 = (tile == 0) ? row0 : col0;
#pragma unroll
            for (int i = 0; i < 2; i++) {
                int idx = i * 256 + tid;          // 0..511 16B chunks
                int row = idx >> 2, c = idx & 3;
                cpa16(st + tile * TILEB + sw64(row * 64 + c * 16),
                      src + (size_t)(r0 + row) * DDIM + k + c * 8);
            }
        }
        asm volatile("cp.async.commit_group;" ::: "memory");
    };

    load_stage(0, 0);
    load_stage(1, 32);
    load_stage(2, 64);

    for (int kb = 0; kb < 32; kb++) {
        if (kb <= 29)      asm volatile("cp.async.wait_group 2;" ::: "memory");
        else if (kb == 30) asm volatile("cp.async.wait_group 1;" ::: "memory");
        else               asm volatile("cp.async.wait_group 0;" ::: "memory");
        __syncthreads();   // stage kb visible; also fences reads of stage (kb-1)&3

        const uint32_t st = sb + (kb & 3) * STAGE;
        const uint32_t Ah = st, Bhs = st + TILEB, Bls = st + 2 * TILEB;
#pragma unroll
        for (int s = 0; s < 2; s++) {                 // two k16 steps in BK=32
            uint32_t ah[2][4];
#pragma unroll
            for (int mi = 0; mi < 2; mi++)
                ldsm4(ah[mi], Ah + aswz[mi][s]);
#pragma unroll
            for (int j = 0; j < 4; j++) {
                uint32_t bh[4], bl[4];
                ldsm4(bh, Bhs + bswz[j][s]);
                ldsm4(bl, Bls + bswz[j][s]);
#pragma unroll
                for (int mi = 0; mi < 2; mi++)
#pragma unroll
                    for (int t = 0; t < 2; t++) {
                        mma16816(acc[mi][j * 2 + t], ah[mi], &bh[t * 2]);
                        mma16816(acc[mi][j * 2 + t], ah[mi], &bl[t * 2]);
                    }
            }
        }
        if (kb + 3 < 32) load_stage((kb + 3) & 3, (kb + 3) * 32);
    }

    // ---------------- epilogue ------------------------------------------------
    // thread's elements: rows (row0 + wm*32 + mi*16 + lane/4 + {0,8}),
    //                    cols (col0 + wn*64 + ni*8 + (lane&3)*2 + {0,1})
    if (MODE == 0) {
        float* red = (float*)(smem + RED_OFF);
        float s[2][2] = {{0.f, 0.f}, {0.f, 0.f}};
#pragma unroll
        for (int mi = 0; mi < 2; mi++)
#pragma unroll
            for (int ni = 0; ni < 8; ni++) {
                int cl = wn * 64 + ni * 8 + (lane & 3) * 2;
                float m0 = pm[cl], m1 = pm[cl + 1];
                float c0 = ps[cl], c1 = ps[cl + 1];
                float b0 = pb[cl], b1 = pb[cl + 1];
                float h;
                h = (acc[mi][ni][0] - m0) * c0 + b0; s[mi][0] += 1.f / (1.f + __expf(4.f - 4.f * h));
                h = (acc[mi][ni][1] - m1) * c1 + b1; s[mi][0] += 1.f / (1.f + __expf(4.f - 4.f * h));
                h = (acc[mi][ni][2] - m0) * c0 + b0; s[mi][1] += 1.f / (1.f + __expf(4.f - 4.f * h));
                h = (acc[mi][ni][3] - m1) * c1 + b1; s[mi][1] += 1.f / (1.f + __expf(4.f - 4.f * h));
            }
        __syncthreads();   // mainloop smem reads done before red[] reuse
#pragma unroll
        for (int mi = 0; mi < 2; mi++)
#pragma unroll
            for (int hh = 0; hh < 2; hh++) {
                float v = s[mi][hh];
                v += __shfl_xor_sync(0xffffffffu, v, 1);
                v += __shfl_xor_sync(0xffffffffu, v, 2);
                if ((lane & 3) == 0)
                    red[wn * 128 + wm * 32 + mi * 16 + hh * 8 + (lane >> 2)] = v;
            }
        __syncthreads();
        if (tid < 128)
            part[(size_t)(row0 + tid) * 8 + bc] = red[tid] + red[128 + tid];
    } else if (MODE == 1) {
#pragma unroll
        for (int mi = 0; mi < 2; mi++) {
            int r = row0 + wm * 32 + mi * 16 + (lane >> 2);
#pragma unroll
            for (int ni = 0; ni < 8; ni++) {
                int cl = wn * 64 + ni * 8 + (lane & 3) * 2;
                int col = col0 + cl;
#pragma unroll
                for (int p = 0; p < 2; p++) {
                    float h0 = (acc[mi][ni][p * 2 + 0] - pm[cl]) * ps[cl] + pb[cl];
                    float h1 = (acc[mi][ni][p * 2 + 1] - pm[cl + 1]) * ps[cl + 1] + pb[cl + 1];
                    float v0 = 1.f / (1.f + __expf(4.f - 4.f * h0));
                    float v1 = 1.f / (1.f + __expf(4.f - 4.f * h1));
                    size_t off = (size_t)(r + p * 8) * DDIM + col;
                    *(uint32_t*)(g_Vh + off) = h2(v0, v1);
                }
            }
        }
    } else {
#pragma unroll
        for (int mi = 0; mi < 2; mi++) {
            int r = row0 + wm * 32 + mi * 16 + (lane >> 2);
#pragma unroll
            for (int ni = 0; ni < 8; ni++) {
                int col = col0 + wn * 64 + ni * 8 + (lane & 3) * 2;
                *(float2*)(g_VW + (size_t)r * DDIM + col) =
                    make_float2(acc[mi][ni][0], acc[mi][ni][1]);
                *(float2*)(g_VW + (size_t)(r + 8) * DDIM + col) =
                    make_float2(acc[mi][ni][2], acc[mi][ni][3]);
            }
        }
    }
}

// ---------------- t = 1 - mean ----------------------------------------------
__global__ void reduce_t_kernel() {
    int i = blockIdx.x * blockDim.x + threadIdx.x;
    if (i < MROWS) {
        float sq = 0.0f, sk = 0.0f;
#pragma unroll
        for (int j = 0; j < 8; j++) { sq += g_qpart[i * 8 + j]; sk += g_kpart[i * 8 + j]; }
        g_tQ[i] = 1.0f - sq * (1.0f / 1024.0f);
        g_tK[i] = 1.0f - sk * (1.0f / 1024.0f);
    }
}

// ---------------- bitonic sort per batch: y=0 -> tK, y=1 -> tQ ---------------
__global__ void __launch_bounds__(1024) sort_kernel() {
    __shared__ float sv[NSEQ];
    __shared__ int   si[NSEQ];
    const int b = blockIdx.x, t = threadIdx.x;
    const float* src = (blockIdx.y == 0) ? g_tK : g_tQ;
    sv[t]        = src[b * NSEQ + t];        si[t]        = t;
    sv[t + 1024] = src[b * NSEQ + t + 1024]; si[t + 1024] = t + 1024;
    __syncthreads();
    for (int k = 2; k <= NSEQ; k <<= 1) {
        for (int j = k >> 1; j > 0; j >>= 1) {
#pragma unroll
            for (int l = 0; l < 2; l++) {
                int idx = t + l * 1024;
                int ixj = idx ^ j;
                if (ixj > idx) {
                    bool asc = ((idx & k) == 0);
                    float a = sv[idx], bvv = sv[ixj];
                    if ((a > bvv) == asc) {
                        sv[idx] = bvv; sv[ixj] = a;
                        int tmp = si[idx]; si[idx] = si[ixj]; si[ixj] = tmp;
                    }
                }
            }
            __syncthreads();
        }
    }
    if (blockIdx.y == 0) {
#pragma unroll
        for (int l = 0; l < 2; l++) {
            int idx = t + l * 1024;
            float tk = sv[idx];
            g_tKs [b * NSEQ + idx] = tk;
            g_perm[b * NSEQ + idx] = si[idx];
            g_E1  [b * NSEQ + idx] = expf( 2.0f * tk);
            g_E2  [b * NSEQ + idx] = expf(-2.0f * tk);
        }
    } else {
#pragma unroll
        for (int l = 0; l < 2; l++) {
            int idx = t + l * 1024;
            g_tQs [b * NSEQ + idx] = sv[idx];
            g_qrow[b * NSEQ + idx] = si[idx];
        }
    }
}

// ---------------- ranks of sorted queries ------------------------------------
__global__ void __launch_bounds__(1024) rank_kernel() {
    int i = blockIdx.x * 1024 + threadIdx.x;      // 0..16383 over (b, sorted j)
    int b = i >> 11;
    float tq = g_tQs[i];
    const float* ks = g_tKs + b * NSEQ;
    int lo = 0, hi = NSEQ;
    while (lo < hi) {                 // upper_bound: count of tK <= tQ
        int mid = (lo + hi) >> 1;
        if (ks[mid] <= tq) lo = mid + 1; else hi = mid;
    }
    g_rank[i] = lo;
}

// ---------------- segmented scan: pass A (per-segment totals) ---------------
__global__ void __launch_bounds__(1024) scanA_kernel() {
    const int seg = blockIdx.x, b = blockIdx.y, d = threadIdx.x;
    const int base = b * NSEQ + seg * SEGLEN;
    float a0 = 0.0f, a1 = 0.0f, a2 = 0.0f;
#pragma unroll 4
    for (int p = 0; p < SEGLEN; p++) {
        int   r  = g_perm[base + p];
        float w1 = g_E1[base + p];
        float w2 = g_E2[base + p];
        float v  = g_VW[((size_t)b * NSEQ + r) * DDIM + d];
        a0 += v; a1 += w1 * v; a2 += w2 * v;
    }
    size_t o = ((size_t)(b * NSEG + seg)) * DDIM + d;
    g_s0[o] = a0; g_s1[o] = a1; g_s2[o] = a2;
}

// ---------------- pass B: exclusive offsets + totals --------------------------
__global__ void __launch_bounds__(1024) scanB_kernel() {
    const int b = blockIdx.x, d = threadIdx.x;
    float o0 = 0.0f, o1 = 0.0f, o2 = 0.0f;
#pragma unroll 4
    for (int s = 0; s < NSEG; s++) {
        size_t i = ((size_t)(b * NSEG + s)) * DDIM + d;
        float t0 = g_s0[i], t1 = g_s1[i], t2 = g_s2[i];
        g_s1[i] = o1; g_s2[i] = o2;          // overwrite with exclusive offsets
        o0 += t0; o1 += t1; o2 += t2;
    }
    g_vsum[b * DDIM + d] = o0;
    g_tot2[b * DDIM + d] = o2;
}

// ---------------- pass C fused with output emission --------------------------
__global__ void __launch_bounds__(1024) fusedC_kernel(const float* __restrict__ bo,
                                                      float* __restrict__ out) {
    const int seg = blockIdx.x, b = blockIdx.y, d = threadIdx.x;
    const int base = b * NSEQ + seg * SEGLEN;
    __shared__ int sh_jlo, sh_jhi;

    if (d == 0) {
        const int* rk = g_rank + b * NSEQ;
        const int rlo = seg * SEGLEN;
        const int rhi = (seg == NSEG - 1) ? (NSEQ + 1) : (seg + 1) * SEGLEN;
        int lo = 0, hi = NSEQ;
        while (lo < hi) { int m = (lo + hi) >> 1; if (rk[m] < rlo) lo = m + 1; else hi = m; }
        sh_jlo = lo;
        lo = 0; hi = NSEQ;
        while (lo < hi) { int m = (lo + hi) >> 1; if (rk[m] < rhi) lo = m + 1; else hi = m; }
        sh_jhi = lo;
    }
    __syncthreads();
    int jcur = sh_jlo;
    const int jhi = sh_jhi;

    size_t so = ((size_t)(b * NSEG + seg)) * DDIM + d;
    float a1 = g_s1[so], a2 = g_s2[so];
    const float tot2 = g_tot2[b * DDIM + d];
    const float vs   = g_vsum[b * DDIM + d];
    const float bb   = bo[d];
    const float A_STDP = 0.9f, W_OFF = 0.9f;

    for (int p = 0; p < SEGLEN; p++) {
        const int grank = seg * SEGLEN + p;
        while (jcur < jhi && g_rank[b * NSEQ + jcur] == grank) {
            float tq = g_tQs[b * NSEQ + jcur];
            int   qi = g_qrow[b * NSEQ + jcur];
            float e2  = expf( 2.0f * tq);
            float em2 = expf(-2.0f * tq);
            out[((size_t)b * NSEQ + qi) * DDIM + d] =
                A_STDP * (e2 * (tot2 - a2) - em2 * a1) + W_OFF * vs + bb;
            jcur++;
        }
        int   r  = g_perm[base + p];
        float w1 = g_E1[base + p];
        float w2 = g_E2[base + p];
        float v  = g_VW[((size_t)b * NSEQ + r) * DDIM + d];
        a1 += w1 * v; a2 += w2 * v;
    }
    while (jcur < jhi) {
        float tq = g_tQs[b * NSEQ + jcur];
        int   qi = g_qrow[b * NSEQ + jcur];
        float e2  = expf( 2.0f * tq);
        float em2 = expf(-2.0f * tq);
        out[((size_t)b * NSEQ + qi) * DDIM + d] =
            A_STDP * (e2 * (tot2 - a2) - em2 * a1) + W_OFF * vs + bb;
        jcur++;
    }
}

// -----------------------------------------------------------------------------
extern "C" void kernel_launch(void* const* d_in, const int* in_sizes, int n_in,
                              void* d_out, int out_size) {
    const float* x  = (const float*)d_in[0];
    const float* Wq = (const float*)d_in[1];
    const float* gq = (const float*)d_in[2];
    const float* bq = (const float*)d_in[3];
    const float* mq = (const float*)d_in[4];
    const float* vq = (const float*)d_in[5];
    const float* Wk = (const float*)d_in[6];
    const float* gk = (const float*)d_in[7];
    const float* bk = (const float*)d_in[8];
    const float* mk = (const float*)d_in[9];
    const float* vk = (const float*)d_in[10];
    const float* Wv = (const float*)d_in[11];
    const float* gv = (const float*)d_in[12];
    const float* bv = (const float*)d_in[13];
    const float* mv = (const float*)d_in[14];
    const float* vv = (const float*)d_in[15];
    const float* Wo = (const float*)d_in[16];
    const float* bo = (const float*)d_in[17];
    float* out = (float*)d_out;

    cudaFuncSetAttribute(tc_gemm<0>, cudaFuncAttributeMaxDynamicSharedMemorySize, GEMM_SMEM);
    cudaFuncSetAttribute(tc_gemm<1>, cudaFuncAttributeMaxDynamicSharedMemorySize, GEMM_SMEM);
    cudaFuncSetAttribute(tc_gemm<2>, cudaFuncAttributeMaxDynamicSharedMemorySize, GEMM_SMEM);

    __half *xh, *wh, *wl, *vh;
    float *qp, *kp;
    cudaGetSymbolAddress((void**)&xh, g_xh);
    cudaGetSymbolAddress((void**)&wh, g_Wh);
    cudaGetSymbolAddress((void**)&wl, g_Wl);
    cudaGetSymbolAddress((void**)&vh, g_Vh);
    cudaGetSymbolAddress((void**)&qp, g_qpart);
    cudaGetSymbolAddress((void**)&kp, g_kpart);

    prep_x<<<MROWS * DDIM / 1024, 256>>>(x);
    prep_w<<<dim3(32, 32, 4), dim3(32, 8)>>>(Wq, Wk, Wv, Wo);

    const size_t WSZ = (size_t)DDIM * DDIM;
    // fused Q+K (z selects weight/BN set)
    tc_gemm<0><<<dim3(8, 128, 2), 256, GEMM_SMEM>>>(
        xh, wh + 0 * WSZ, wl + 0 * WSZ,
        mq, gq, vq, bq, qp,
        mk, gk, vk, bk, kp);
    tc_gemm<1><<<dim3(8, 128, 1), 256, GEMM_SMEM>>>(
        xh, wh + 2 * WSZ, wl + 2 * WSZ,
        mv, gv, vv, bv, nullptr,
        nullptr, nullptr, nullptr, nullptr, nullptr);
    tc_gemm<2><<<dim3(8, 128, 1), 256, GEMM_SMEM>>>(
        vh, wh + 3 * WSZ, wl + 3 * WSZ,
        nullptr, nullptr, nullptr, nullptr, nullptr,
        nullptr, nullptr, nullptr, nullptr, nullptr);

    reduce_t_kernel<<<64, 256>>>();
    sort_kernel<<<dim3(NBATCH, 2), 1024>>>();
    rank_kernel<<<16, 1024>>>();
    scanA_kernel<<<dim3(NSEG, NBATCH), 1024>>>();
    scanB_kernel<<<NBATCH, 1024>>>();
    fusedC_kernel<<<dim3(NSEG, NBATCH), 1024>>>(bo, out);
}

// round 16
// speedup vs baseline: 1.0060x; 1.0060x over previous
#include <cuda_runtime.h>
#include <cuda_fp16.h>
#include <stdint.h>
#include <math.h>

#define MROWS 16384   // B*N
#define DDIM  1024
#define NSEQ  2048
#define NBATCH 8
#define NSEG  32
#define SEGLEN 64     // NSEQ / NSEG

// ---------------- scratch (device globals) ---------------------------------
__device__ __half g_xh[MROWS * DDIM];            // fp16(x)
__device__ __half g_Wh[4 * DDIM * DDIM];         // transposed weights [n][k], fp16 hi
__device__ __half g_Wl[4 * DDIM * DDIM];         // fp16 residual
__device__ __half g_Vh[MROWS * DDIM];            // fp16(V)
__device__ float g_VW[MROWS * DDIM];
__device__ float g_qpart[MROWS * 8];
__device__ float g_kpart[MROWS * 8];
__device__ float g_tQ[MROWS];
__device__ float g_tK[MROWS];
__device__ float g_tKs[NBATCH * NSEQ];      // sorted tK
__device__ float g_E1[NBATCH * NSEQ];       // e^{+2 tKs}
__device__ float g_E2[NBATCH * NSEQ];       // e^{-2 tKs}
__device__ int   g_perm[NBATCH * NSEQ];     // K sort permutation
__device__ float g_tQs[NBATCH * NSEQ];      // sorted tQ
__device__ int   g_qrow[NBATCH * NSEQ];     // Q sort permutation (orig row in batch)
__device__ int   g_rank[NBATCH * NSEQ];     // rank of sorted query
__device__ float g_vsum[NBATCH * DDIM];     // total colsum of VW
__device__ float g_tot2[NBATCH * DDIM];     // total e^{-2tK}-weighted colsum
__device__ float g_s0[NBATCH * NSEG * DDIM];
__device__ float g_s1[NBATCH * NSEG * DDIM];
__device__ float g_s2[NBATCH * NSEG * DDIM];

// ---------------- PTX helpers (base sm_103 target only!) -------------------
__device__ __forceinline__ uint32_t smem_u32(const void* p) {
    uint32_t a;
    asm("{ .reg .u64 t; cvta.to.shared.u64 t, %1; cvt.u32.u64 %0, t; }"
        : "=r"(a) : "l"(p));
    return a;
}
__device__ __forceinline__ void ldsm4(uint32_t* r, uint32_t a) {
    asm volatile("ldmatrix.sync.aligned.m8n8.x4.shared.b16 {%0,%1,%2,%3}, [%4];"
        : "=r"(r[0]), "=r"(r[1]), "=r"(r[2]), "=r"(r[3]) : "r"(a));
}
__device__ __forceinline__ void mma16816(float* c, const uint32_t* a, const uint32_t* b) {
    asm volatile("mma.sync.aligned.m16n8k16.row.col.f32.f16.f16.f32 "
        "{%0,%1,%2,%3},{%4,%5,%6,%7},{%8,%9},{%0,%1,%2,%3};"
        : "+f"(c[0]), "+f"(c[1]), "+f"(c[2]), "+f"(c[3])
        : "r"(a[0]), "r"(a[1]), "r"(a[2]), "r"(a[3]), "r"(b[0]), "r"(b[1]));
}
__device__ __forceinline__ void cpa16(uint32_t dst, const void* src) {
    asm volatile("cp.async.cg.shared.global [%0], [%1], 16;" :: "r"(dst), "l"(src));
}
__device__ __forceinline__ uint32_t h2(float a, float b) {
    __half2 t = __floats2half2_rn(a, b);
    return *reinterpret_cast<uint32_t*>(&t);
}
__device__ __forceinline__ uint32_t sw64(uint32_t off) {
    return off ^ ((off >> 3) & 0x30);
}

// ---------------- prep: x -> fp16 -------------------------------------------
__global__ void __launch_bounds__(256) prep_x(const float* __restrict__ x) {
    size_t i = ((size_t)blockIdx.x * 256 + threadIdx.x) * 4;
    float4 v = *(const float4*)(x + i);
    uint2 o = make_uint2(h2(v.x, v.y), h2(v.z, v.w));
    *(uint2*)(g_xh + i) = o;
}

// ---------------- prep: transpose W -> fp16 hi/lo [n][k] ---------------------
__global__ void __launch_bounds__(256) prep_w(const float* W0, const float* W1,
                                              const float* W2, const float* W3) {
    __shared__ float t[32][33];
    const float* W = blockIdx.z == 0 ? W0 : blockIdx.z == 1 ? W1
                   : blockIdx.z == 2 ? W2 : W3;
    __half* oh = g_Wh + (size_t)blockIdx.z * DDIM * DDIM;
    __half* ol = g_Wl + (size_t)blockIdx.z * DDIM * DDIM;
    int n0 = blockIdx.x * 32, k0 = blockIdx.y * 32;
    int tx = threadIdx.x, ty = threadIdx.y;       // 32 x 8
#pragma unroll
    for (int j = 0; j < 4; j++)
        t[ty + j * 8][tx] = W[(size_t)(k0 + ty + j * 8) * DDIM + n0 + tx];
    __syncthreads();
#pragma unroll
    for (int j = 0; j < 4; j++) {
        int nn = ty + j * 8;
        float v = t[tx][nn];                      // = W[k0+tx][n0+nn]
        __half h = __float2half_rn(v);
        oh[(size_t)(n0 + nn) * DDIM + k0 + tx] = h;
        ol[(size_t)(n0 + nn) * DDIM + k0 + tx] =
            __float2half_rn(v - __half2float(h));
    }
}

// ---------------- HMMA GEMM: 128x128 tile, BK=32, fp16 A + 2-term fp16 B -----
// SW64-swizzled 64B rows, 4-stage cp.async (&3), single sync/iter, 2 CTAs/SM.
// MODE 0: BN+sigmoid -> row sums; fused Q/K via blockIdx.z
// MODE 1: BN+sigmoid -> g_Vh (fp16)
// MODE 2: plain -> g_VW (fp32)
#define TILEB  8192                    // 128 rows * 64B (32 fp16 cols)
#define STAGE  (3 * TILEB)             // 24576 (A, Bh, Bl)
#define NSTG   4
#define BN_OFF (NSTG * STAGE)          // 98304
#define RED_OFF (BN_OFF + 3 * 128 * 4) // 99840
#define GEMM_SMEM (RED_OFF + 256 * 4)  // 100864

template <int MODE>
__global__ void __launch_bounds__(256, 2)
tc_gemm(const __half* __restrict__ A, const __half* __restrict__ Bh0,
        const __half* __restrict__ Bl0,
        const float* __restrict__ mean, const float* __restrict__ gam,
        const float* __restrict__ var, const float* __restrict__ beta,
        float* __restrict__ part,
        const float* __restrict__ mean2, const float* __restrict__ gam2,
        const float* __restrict__ var2, const float* __restrict__ beta2,
        float* __restrict__ part2)
{
    extern __shared__ char smem[];
    const uint32_t sb = smem_u32(smem);
    const int tid = threadIdx.x, lane = tid & 31, wid = tid >> 5;
    const int wm = wid & 3, wn = wid >> 2;        // 4 (M) x 2 (N) warps
    const int bc = blockIdx.x, br = blockIdx.y;
    const int row0 = br * 128, col0 = bc * 128;

    const __half* Bh = Bh0;
    const __half* Bl = Bl0;
    if (MODE == 0 && blockIdx.z == 1) {
        Bh += (size_t)DDIM * DDIM; Bl += (size_t)DDIM * DDIM;
        mean = mean2; gam = gam2; var = var2; beta = beta2; part = part2;
    }

    float* pm = (float*)(smem + BN_OFF);
    float* ps = pm + 128;
    float* pb = ps + 128;
    if (MODE != 2 && tid < 128) {
        pm[tid] = mean[col0 + tid];
        ps[tid] = gam[col0 + tid] * rsqrtf(var[col0 + tid] + 1e-5f);
        pb[tid] = beta[col0 + tid];
    }

    // precomputed swizzled ldmatrix offsets (per-thread loop invariants)
    uint32_t aswz[2][2], bswz[4][2];
#pragma unroll
    for (int mi = 0; mi < 2; mi++)
#pragma unroll
        for (int s = 0; s < 2; s++)
            aswz[mi][s] = sw64((uint32_t)((wm * 32 + mi * 16 + (lane & 15)) * 64
                                          + (2 * s + (lane >> 4)) * 16));
#pragma unroll
    for (int j = 0; j < 4; j++)
#pragma unroll
        for (int s = 0; s < 2; s++)
            bswz[j][s] = sw64((uint32_t)((wn * 64 + j * 16 + (lane & 7) + ((lane >> 4) << 3)) * 64
                                         + (2 * s + ((lane >> 3) & 1)) * 16));

    float acc[2][8][4];
#pragma unroll
    for (int a = 0; a < 2; a++)
#pragma unroll
        for (int b = 0; b < 8; b++)
#pragma unroll
            for (int q = 0; q < 4; q++) acc[a][b][q] = 0.0f;

    // stage loader: 3 tiles of 128x32 fp16
    auto load_stage = [&](int stg, int k) {
        const uint32_t st = sb + stg * STAGE;
#pragma unroll
        for (int tile = 0; tile < 3; tile++) {
            const __half* src = (tile == 0) ? A : (tile == 1) ? Bh : Bl;
            const int r0 = (tile == 0) ? row0 : col0;
#pragma unroll
            for (int i = 0; i < 2; i++) {
                int idx = i * 256 + tid;          // 0..511 16B chunks
                int row = idx >> 2, c = idx & 3;
                cpa16(st + tile * TILEB + sw64(row * 64 + c * 16),
                      src + (size_t)(r0 + row) * DDIM + k + c * 8);
            }
        }
        asm volatile("cp.async.commit_group;" ::: "memory");
    };

    load_stage(0, 0);
    load_stage(1, 32);
    load_stage(2, 64);

    for (int kb = 0; kb < 32; kb++) {
        if (kb <= 29)      asm volatile("cp.async.wait_group 2;" ::: "memory");
        else if (kb == 30) asm volatile("cp.async.wait_group 1;" ::: "memory");
        else               asm volatile("cp.async.wait_group 0;" ::: "memory");
        __syncthreads();   // stage kb visible; also fences reads of stage (kb-1)&3

        const uint32_t st = sb + (kb & 3) * STAGE;
        const uint32_t Ah = st, Bhs = st + TILEB, Bls = st + 2 * TILEB;
#pragma unroll
        for (int s = 0; s < 2; s++) {                 // two k16 steps in BK=32
            uint32_t ah[2][4];
#pragma unroll
            for (int mi = 0; mi < 2; mi++)
                ldsm4(ah[mi], Ah + aswz[mi][s]);
#pragma unroll
            for (int j = 0; j < 4; j++) {
                uint32_t bh[4], bl[4];
                ldsm4(bh, Bhs + bswz[j][s]);
                ldsm4(bl, Bls + bswz[j][s]);
#pragma unroll
                for (int mi = 0; mi < 2; mi++)
#pragma unroll
                    for (int t = 0; t < 2; t++) {
                        mma16816(acc[mi][j * 2 + t], ah[mi], &bh[t * 2]);
                        mma16816(acc[mi][j * 2 + t], ah[mi], &bl[t * 2]);
                    }
            }
        }
        if (kb + 3 < 32) load_stage((kb + 3) & 3, (kb + 3) * 32);
    }

    // ---------------- epilogue ------------------------------------------------
    // thread's elements: rows (row0 + wm*32 + mi*16 + lane/4 + {0,8}),
    //                    cols (col0 + wn*64 + ni*8 + (lane&3)*2 + {0,1})
    if (MODE == 0) {
        float* red = (float*)(smem + RED_OFF);
        float s[2][2] = {{0.f, 0.f}, {0.f, 0.f}};
#pragma unroll
        for (int mi = 0; mi < 2; mi++)
#pragma unroll
            for (int ni = 0; ni < 8; ni++) {
                int cl = wn * 64 + ni * 8 + (lane & 3) * 2;
                float m0 = pm[cl], m1 = pm[cl + 1];
                float c0 = ps[cl], c1 = ps[cl + 1];
                float b0 = pb[cl], b1 = pb[cl + 1];
                float h;
                h = (acc[mi][ni][0] - m0) * c0 + b0; s[mi][0] += 1.f / (1.f + __expf(4.f - 4.f * h));
                h = (acc[mi][ni][1] - m1) * c1 + b1; s[mi][0] += 1.f / (1.f + __expf(4.f - 4.f * h));
                h = (acc[mi][ni][2] - m0) * c0 + b0; s[mi][1] += 1.f / (1.f + __expf(4.f - 4.f * h));
                h = (acc[mi][ni][3] - m1) * c1 + b1; s[mi][1] += 1.f / (1.f + __expf(4.f - 4.f * h));
            }
        __syncthreads();   // mainloop smem reads done before red[] reuse
#pragma unroll
        for (int mi = 0; mi < 2; mi++)
#pragma unroll
            for (int hh = 0; hh < 2; hh++) {
                float v = s[mi][hh];
                v += __shfl_xor_sync(0xffffffffu, v, 1);
                v += __shfl_xor_sync(0xffffffffu, v, 2);
                if ((lane & 3) == 0)
                    red[wn * 128 + wm * 32 + mi * 16 + hh * 8 + (lane >> 2)] = v;
            }
        __syncthreads();
        if (tid < 128)
            part[(size_t)(row0 + tid) * 8 + bc] = red[tid] + red[128 + tid];
    } else if (MODE == 1) {
#pragma unroll
        for (int mi = 0; mi < 2; mi++) {
            int r = row0 + wm * 32 + mi * 16 + (lane >> 2);
#pragma unroll
            for (int ni = 0; ni < 8; ni++) {
                int cl = wn * 64 + ni * 8 + (lane & 3) * 2;
                int col = col0 + cl;
#pragma unroll
                for (int p = 0; p < 2; p++) {
                    float h0 = (acc[mi][ni][p * 2 + 0] - pm[cl]) * ps[cl] + pb[cl];
                    float h1 = (acc[mi][ni][p * 2 + 1] - pm[cl + 1]) * ps[cl + 1] + pb[cl + 1];
                    float v0 = 1.f / (1.f + __expf(4.f - 4.f * h0));
                    float v1 = 1.f / (1.f + __expf(4.f - 4.f * h1));
                    size_t off = (size_t)(r + p * 8) * DDIM + col;
                    *(uint32_t*)(g_Vh + off) = h2(v0, v1);
                }
            }
        }
    } else {
#pragma unroll
        for (int mi = 0; mi < 2; mi++) {
            int r = row0 + wm * 32 + mi * 16 + (lane >> 2);
#pragma unroll
            for (int ni = 0; ni < 8; ni++) {
                int col = col0 + wn * 64 + ni * 8 + (lane & 3) * 2;
                *(float2*)(g_VW + (size_t)r * DDIM + col) =
                    make_float2(acc[mi][ni][0], acc[mi][ni][1]);
                *(float2*)(g_VW + (size_t)(r + 8) * DDIM + col) =
                    make_float2(acc[mi][ni][2], acc[mi][ni][3]);
            }
        }
    }
}

// ---------------- t = 1 - mean ----------------------------------------------
__global__ void reduce_t_kernel() {
    int i = blockIdx.x * blockDim.x + threadIdx.x;
    if (i < MROWS) {
        float sq = 0.0f, sk = 0.0f;
#pragma unroll
        for (int j = 0; j < 8; j++) { sq += g_qpart[i * 8 + j]; sk += g_kpart[i * 8 + j]; }
        g_tQ[i] = 1.0f - sq * (1.0f / 1024.0f);
        g_tK[i] = 1.0f - sk * (1.0f / 1024.0f);
    }
}

// ---------------- bitonic sort per batch: y=0 -> tK, y=1 -> tQ ---------------
__global__ void __launch_bounds__(1024) sort_kernel() {
    __shared__ float sv[NSEQ];
    __shared__ int   si[NSEQ];
    const int b = blockIdx.x, t = threadIdx.x;
    const float* src = (blockIdx.y == 0) ? g_tK : g_tQ;
    sv[t]        = src[b * NSEQ + t];        si[t]        = t;
    sv[t + 1024] = src[b * NSEQ + t + 1024]; si[t + 1024] = t + 1024;
    __syncthreads();
    for (int k = 2; k <= NSEQ; k <<= 1) {
        for (int j = k >> 1; j > 0; j >>= 1) {
#pragma unroll
            for (int l = 0; l < 2; l++) {
                int idx = t + l * 1024;
                int ixj = idx ^ j;
                if (ixj > idx) {
                    bool asc = ((idx & k) == 0);
                    float a = sv[idx], bvv = sv[ixj];
                    if ((a > bvv) == asc) {
                        sv[idx] = bvv; sv[ixj] = a;
                        int tmp = si[idx]; si[idx] = si[ixj]; si[ixj] = tmp;
                    }
                }
            }
            __syncthreads();
        }
    }
    if (blockIdx.y == 0) {
#pragma unroll
        for (int l = 0; l < 2; l++) {
            int idx = t + l * 1024;
            float tk = sv[idx];
            g_tKs [b * NSEQ + idx] = tk;
            g_perm[b * NSEQ + idx] = si[idx];
            g_E1  [b * NSEQ + idx] = expf( 2.0f * tk);
            g_E2  [b * NSEQ + idx] = expf(-2.0f * tk);
        }
    } else {
#pragma unroll
        for (int l = 0; l < 2; l++) {
            int idx = t + l * 1024;
            g_tQs [b * NSEQ + idx] = sv[idx];
            g_qrow[b * NSEQ + idx] = si[idx];
        }
    }
}

// ---------------- ranks of sorted queries ------------------------------------
__global__ void __launch_bounds__(1024) rank_kernel() {
    int i = blockIdx.x * 1024 + threadIdx.x;      // 0..16383 over (b, sorted j)
    int b = i >> 11;
    float tq = g_tQs[i];
    const float* ks = g_tKs + b * NSEQ;
    int lo = 0, hi = NSEQ;
    while (lo < hi) {                 // upper_bound: count of tK <= tQ
        int mid = (lo + hi) >> 1;
        if (ks[mid] <= tq) lo = mid + 1; else hi = mid;
    }
    g_rank[i] = lo;
}

// ---------------- segmented scan: pass A (per-segment totals) ---------------
__global__ void __launch_bounds__(1024) scanA_kernel() {
    const int seg = blockIdx.x, b = blockIdx.y, d = threadIdx.x;
    const int base = b * NSEQ + seg * SEGLEN;
    float a0 = 0.0f, a1 = 0.0f, a2 = 0.0f;
#pragma unroll 4
    for (int p = 0; p < SEGLEN; p++) {
        int   r  = g_perm[base + p];
        float w1 = g_E1[base + p];
        float w2 = g_E2[base + p];
        float v  = g_VW[((size_t)b * NSEQ + r) * DDIM + d];
        a0 += v; a1 += w1 * v; a2 += w2 * v;
    }
    size_t o = ((size_t)(b * NSEG + seg)) * DDIM + d;
    g_s0[o] = a0; g_s1[o] = a1; g_s2[o] = a2;
}

// ---------------- pass B: exclusive offsets + totals --------------------------
__global__ void __launch_bounds__(1024) scanB_kernel() {
    const int b = blockIdx.x, d = threadIdx.x;
    float o0 = 0.0f, o1 = 0.0f, o2 = 0.0f;
#pragma unroll 4
    for (int s = 0; s < NSEG; s++) {
        size_t i = ((size_t)(b * NSEG + s)) * DDIM + d;
        float t0 = g_s0[i], t1 = g_s1[i], t2 = g_s2[i];
        g_s1[i] = o1; g_s2[i] = o2;          // overwrite with exclusive offsets
        o0 += t0; o1 += t1; o2 += t2;
    }
    g_vsum[b * DDIM + d] = o0;
    g_tot2[b * DDIM + d] = o2;
}

// ---------------- pass C fused with output emission --------------------------
__global__ void __launch_bounds__(1024) fusedC_kernel(const float* __restrict__ bo,
                                                      float* __restrict__ out) {
    const int seg = blockIdx.x, b = blockIdx.y, d = threadIdx.x;
    const int base = b * NSEQ + seg * SEGLEN;
    __shared__ int sh_jlo, sh_jhi;

    if (d == 0) {
        const int* rk = g_rank + b * NSEQ;
        const int rlo = seg * SEGLEN;
        const int rhi = (seg == NSEG - 1) ? (NSEQ + 1) : (seg + 1) * SEGLEN;
        int lo = 0, hi = NSEQ;
        while (lo < hi) { int m = (lo + hi) >> 1; if (rk[m] < rlo) lo = m + 1; else hi = m; }
        sh_jlo = lo;
        lo = 0; hi = NSEQ;
        while (lo < hi) { int m = (lo + hi) >> 1; if (rk[m] < rhi) lo = m + 1; else hi = m; }
        sh_jhi = lo;
    }
    __syncthreads();
    int jcur = sh_jlo;
    const int jhi = sh_jhi;

    size_t so = ((size_t)(b * NSEG + seg)) * DDIM + d;
    float a1 = g_s1[so], a2 = g_s2[so];
    const float tot2 = g_tot2[b * DDIM + d];
    const float vs   = g_vsum[b * DDIM + d];
    const float bb   = bo[d];
    const float A_STDP = 0.9f, W_OFF = 0.9f;

    for (int p = 0; p < SEGLEN; p++) {
        const int grank = seg * SEGLEN + p;
        while (jcur < jhi && g_rank[b * NSEQ + jcur] == grank) {
            float tq = g_tQs[b * NSEQ + jcur];
            int   qi = g_qrow[b * NSEQ + jcur];
            float e2  = expf( 2.0f * tq);
            float em2 = expf(-2.0f * tq);
            out[((size_t)b * NSEQ + qi) * DDIM + d] =
                A_STDP * (e2 * (tot2 - a2) - em2 * a1) + W_OFF * vs + bb;
            jcur++;
        }
        int   r  = g_perm[base + p];
        float w1 = g_E1[base + p];
        float w2 = g_E2[base + p];
        float v  = g_VW[((size_t)b * NSEQ + r) * DDIM + d];
        a1 += w1 * v; a2 += w2 * v;
    }
    while (jcur < jhi) {
        float tq = g_tQs[b * NSEQ + jcur];
        int   qi = g_qrow[b * NSEQ + jcur];
        float e2  = expf( 2.0f * tq);
        float em2 = expf(-2.0f * tq);
        out[((size_t)b * NSEQ + qi) * DDIM + d] =
            A_STDP * (e2 * (tot2 - a2) - em2 * a1) + W_OFF * vs + bb;
        jcur++;
    }
}

// -----------------------------------------------------------------------------
extern "C" void kernel_launch(void* const* d_in, const int* in_sizes, int n_in,
                              void* d_out, int out_size) {
    const float* x  = (const float*)d_in[0];
    const float* Wq = (const float*)d_in[1];
    const float* gq = (const float*)d_in[2];
    const float* bq = (const float*)d_in[3];
    const float* mq = (const float*)d_in[4];
    const float* vq = (const float*)d_in[5];
    const float* Wk = (const float*)d_in[6];
    const float* gk = (const float*)d_in[7];
    const float* bk = (const float*)d_in[8];
    const float* mk = (const float*)d_in[9];
    const float* vk = (const float*)d_in[10];
    const float* Wv = (const float*)d_in[11];
    const float* gv = (const float*)d_in[12];
    const float* bv = (const float*)d_in[13];
    const float* mv = (const float*)d_in[14];
    const float* vv = (const float*)d_in[15];
    const float* Wo = (const float*)d_in[16];
    const float* bo = (const float*)d_in[17];
    float* out = (float*)d_out;

    cudaFuncSetAttribute(tc_gemm<0>, cudaFuncAttributeMaxDynamicSharedMemorySize, GEMM_SMEM);
    cudaFuncSetAttribute(tc_gemm<1>, cudaFuncAttributeMaxDynamicSharedMemorySize, GEMM_SMEM);
    cudaFuncSetAttribute(tc_gemm<2>, cudaFuncAttributeMaxDynamicSharedMemorySize, GEMM_SMEM);

    __half *xh, *wh, *wl, *vh;
    float *qp, *kp;
    cudaGetSymbolAddress((void**)&xh, g_xh);
    cudaGetSymbolAddress((void**)&wh, g_Wh);
    cudaGetSymbolAddress((void**)&wl, g_Wl);
    cudaGetSymbolAddress((void**)&vh, g_Vh);
    cudaGetSymbolAddress((void**)&qp, g_qpart);
    cudaGetSymbolAddress((void**)&kp, g_kpart);

    prep_x<<<MROWS * DDIM / 1024, 256>>>(x);
    prep_w<<<dim3(32, 32, 4), dim3(32, 8)>>>(Wq, Wk, Wv, Wo);

    const size_t WSZ = (size_t)DDIM * DDIM;
    // fused Q+K (z selects weight/BN set)
    tc_gemm<0><<<dim3(8, 128, 2), 256, GEMM_SMEM>>>(
        xh, wh + 0 * WSZ, wl + 0 * WSZ,
        mq, gq, vq, bq, qp,
        mk, gk, vk, bk, kp);
    tc_gemm<1><<<dim3(8, 128, 1), 256, GEMM_SMEM>>>(
        xh, wh + 2 * WSZ, wl + 2 * WSZ,
        mv, gv, vv, bv, nullptr,
        nullptr, nullptr, nullptr, nullptr, nullptr);
    tc_gemm<2><<<dim3(8, 128, 1), 256, GEMM_SMEM>>>(
        vh, wh + 3 * WSZ, wl + 3 * WSZ,
        nullptr, nullptr, nullptr, nullptr, nullptr,
        nullptr, nullptr, nullptr, nullptr, nullptr);

    reduce_t_kernel<<<64, 256>>>();
    sort_kernel<<<dim3(NBATCH, 2), 1024>>>();
    rank_kernel<<<16, 1024>>>();
    scanA_kernel<<<dim3(NSEG, NBATCH), 1024>>>();
    scanB_kernel<<<NBATCH, 1024>>>();
    fusedC_kernel<<<dim3(NSEG, NBATCH), 1024>>>(bo, out);
}